// round 1
// baseline (speedup 1.0000x reference)
#include <cuda_runtime.h>

#define T_LEN 1024
#define B_SZ  64
#define D_DIM 512
#define N_TAG 24

// Output layout (float32): decoded [0,65536) | pot [65536, 65536+1572864) | lens (64) | trans (576)
#define OFF_DECODED 0
#define OFF_POT     (B_SZ * T_LEN)                       // 65536
#define OFF_LENS    (OFF_POT + B_SZ * T_LEN * N_TAG)     // 1638400
#define OFF_TRANS   (OFF_LENS + B_SZ)                    // 1638464

// ---------------------------------------------------------------------------
// Packed f32x2 FMA (sm_103a FFMA2 path — only reachable via PTX)
// ---------------------------------------------------------------------------
__device__ __forceinline__ unsigned long long ffma2(unsigned long long a,
                                                    unsigned long long b,
                                                    unsigned long long c) {
    unsigned long long d;
    asm("fma.rn.f32x2 %0, %1, %2, %3;" : "=l"(d) : "l"(a), "l"(b), "l"(c));
    return d;
}

// ---------------------------------------------------------------------------
// Kernel A: pot[r][n] = x[r,:] . W[:,n] + b[n]  (+ boundaries at t==0 / t==T-1)
// One thread per row. W transposed into SMEM, read as 64-bit broadcast pairs.
// Accumulate in two f32 halves (even/odd k) via fma.rn.f32x2, fold at end.
// ---------------------------------------------------------------------------
__global__ void gemm_pot_kernel(const float* __restrict__ x,
                                const float* __restrict__ W,
                                const float* __restrict__ bias,
                                const float* __restrict__ lb,
                                const float* __restrict__ rb,
                                float* __restrict__ potOut) {
    __shared__ unsigned long long Ws[N_TAG * (D_DIM / 2)];   // 48 KB
    float* Wsf = (float*)Ws;

    int tid = threadIdx.x;
    // Transpose load: Wsf[n*512 + k] = W[k*24 + n]  (coalesced global reads)
    for (int i = tid; i < D_DIM * N_TAG; i += blockDim.x) {
        int k = i / N_TAG;
        int n = i - k * N_TAG;
        Wsf[n * D_DIM + k] = W[i];
    }
    __syncthreads();

    int r = blockIdx.x * blockDim.x + tid;                   // row in [0, 65536)
    const unsigned long long* x2 =
        (const unsigned long long*)(x + (size_t)r * D_DIM);

    unsigned long long acc[N_TAG];
#pragma unroll
    for (int n = 0; n < N_TAG; n++) acc[n] = 0ull;

    for (int kk = 0; kk < D_DIM / 2; kk++) {
        unsigned long long xv = x2[kk];
#pragma unroll
        for (int n = 0; n < N_TAG; n++)
            acc[n] = ffma2(xv, Ws[n * (D_DIM / 2) + kk], acc[n]);
    }

    int t = r & (T_LEN - 1);
    float* outp = potOut + (size_t)r * N_TAG;
#pragma unroll
    for (int n = 0; n < N_TAG; n++) {
        float lo = __uint_as_float((unsigned int)(acc[n] & 0xffffffffull));
        float hi = __uint_as_float((unsigned int)(acc[n] >> 32));
        float s = lo + hi + bias[n];
        if (t == 0)          s += lb[n];
        if (t == T_LEN - 1)  s += rb[n];
        outp[n] = s;
    }
}

// ---------------------------------------------------------------------------
// Kernel B: Viterbi forward + backtrace. One warp (block) per batch element.
// Lane n owns state n; trans[:,n] lives in 24 registers. Backpointers kept
// in SMEM so the backtrace is an LDS chain, not an L2 chain.
// ---------------------------------------------------------------------------
__global__ void __launch_bounds__(32, 1)
viterbi_kernel(const float* __restrict__ pot,
               const float* __restrict__ trans,
               float* __restrict__ decodedOut) {
    __shared__ unsigned char bp_s[(T_LEN - 1) * N_TAG];      // 24552 B

    int b    = blockIdx.x;
    int lane = threadIdx.x;
    int ln   = lane < N_TAG ? lane : (N_TAG - 1);            // lanes 24..31 mirror 23

    const float* potB = pot + (size_t)b * T_LEN * N_TAG;

    float tc[N_TAG];
#pragma unroll
    for (int m = 0; m < N_TAG; m++) tc[m] = trans[m * N_TAG + ln];

    float alpha = potB[ln];

    // pot software pipeline, depth 3 (covers L2 latency)
    float p1 = potB[1 * N_TAG + ln];
    float p2 = potB[2 * N_TAG + ln];
    float p3 = potB[3 * N_TAG + ln];

    for (int t = 1; t < T_LEN; t++) {
        float pcur = p1; p1 = p2; p2 = p3;
        int tl = t + 3 < T_LEN ? t + 3 : T_LEN - 1;
        p3 = potB[tl * N_TAG + ln];

        float s[N_TAG];
        int   idx[N_TAG];
#pragma unroll
        for (int m = 0; m < N_TAG; m++) {
            s[m]   = __shfl_sync(0xffffffffu, alpha, m) + tc[m];
            idx[m] = m;
        }

        // Contiguous-range tournament: pairing (i, i+st) with st doubling.
        // Left operand always covers strictly lower original indices, so
        // strict '>' preserves jnp.argmax first-occurrence tie semantics.
#define VCMP(i, j) { if (s[j] > s[i]) { s[i] = s[j]; idx[i] = idx[j]; } }
#pragma unroll
        for (int st = 1; st < N_TAG; st <<= 1) {
#pragma unroll
            for (int i = 0; i + st < N_TAG; i += 2 * st) VCMP(i, i + st)
        }
#undef VCMP

        alpha = s[0] + pcur;
        if (lane < N_TAG) bp_s[(t - 1) * N_TAG + lane] = (unsigned char)idx[0];
    }

    __syncwarp();   // make bp_s writes visible to lane 0

    // last_tag = first-occurrence argmax over lanes 0..23 of alpha
    float bv = __shfl_sync(0xffffffffu, alpha, 0);
    int   bt = 0;
#pragma unroll
    for (int m = 1; m < N_TAG; m++) {
        float v = __shfl_sync(0xffffffffu, alpha, m);
        if (v > bv) { bv = v; bt = m; }
    }

    if (lane == 0) {
        float* dec = decodedOut + (size_t)b * T_LEN;
        int tag = bt;
        dec[T_LEN - 1] = (float)tag;
        for (int t = T_LEN - 2; t >= 0; t--) {
            tag = bp_s[t * N_TAG + tag];
            dec[t] = (float)tag;
        }
    }
}

// ---------------------------------------------------------------------------
// Kernel C: lens (all T_LEN) and trans copy into the output tail.
// ---------------------------------------------------------------------------
__global__ void tail_kernel(const float* __restrict__ trans,
                            float* __restrict__ out) {
    int i = threadIdx.x;
    if (i < B_SZ)            out[OFF_LENS + i]  = (float)T_LEN;
    if (i < N_TAG * N_TAG)   out[OFF_TRANS + i] = trans[i];
}

// ---------------------------------------------------------------------------
extern "C" void kernel_launch(void* const* d_in, const int* in_sizes, int n_in,
                              void* d_out, int out_size) {
    const float* x     = (const float*)d_in[0];
    const float* W     = (const float*)d_in[1];
    const float* bias  = (const float*)d_in[2];
    const float* trans = (const float*)d_in[3];
    const float* lb    = (const float*)d_in[4];
    const float* rb    = (const float*)d_in[5];

    float* out = (float*)d_out;
    float* pot = out + OFF_POT;

    gemm_pot_kernel<<<(B_SZ * T_LEN) / 256, 256>>>(x, W, bias, lb, rb, pot);
    tail_kernel<<<1, 640>>>(trans, out + OFF_DECODED ? out : out);  // same ptr; keeps signature simple
    viterbi_kernel<<<B_SZ, 32>>>(pot, trans, out + OFF_DECODED);
}